// round 11
// baseline (speedup 1.0000x reference)
#include <cuda_runtime.h>

// out[b,c] = exp( sum_s x[b, chunk_map[c,s]] * wSupp[c,s] )
// B=4096, NCLASS=1000, NSUPP=64, NCHUNK=4096

#define NCLASS 1000
#define NSUPP  64
#define NCHUNK 4096
#define BATCH  4096
#define NB     4       // batch rows per tile (64 KB smem -> 3 CTAs/SM)
#define THREADS 512
#define CHALF  (NCLASS / 2)   // classes per CTA (tail-filling split)

// SoA packed schedule, transposed [chunk][class] for coalesced LDG:
//   g_idx: 8 u16 indices per int4   -> 8 chunks of 8 slots
//   g_w  : 4 f32 weights per float4 -> 16 chunks of 4 slots
// Schedule: slot p of class c prefers an entry with bank group
// (idx&7) == (p + c) & 7, so the 8 lanes of each LDS.128 phase
// (8 consecutive classes) hit 8 distinct bank groups. Overflow entries
// (group count > 8) spill into leftover slots (~13%).
__device__ int4   g_idx[(NSUPP / 8) * NCLASS];
__device__ float4 g_w[(NSUPP / 4) * NCLASS];

// One thread per (class, bank-group). Branch-free: group counts and running
// ranks live in packed 8x8-bit u64 counters; spill slots come from a
// free-slot bitmask popped with ffsll (O(1) per spill, no inner scans).
__global__ void pack_kernel(const float* __restrict__ w,
                            const int* __restrict__ cmap) {
    int t = blockIdx.x * blockDim.x + threadIdx.x;
    if (t >= NCLASS * 8) return;
    int c = t >> 3;
    int g = t & 7;

    const int*   row  = cmap + c * NSUPP;
    const float* wrow = w + c * NSUPP;
    const unsigned long long PRE = 0x0101010101010101ull;

    // pass 1: per-group counts (8 counters x 8 bits in one u64)
    unsigned long long cnt = 0ull;
#pragma unroll 8
    for (int e = 0; e < NSUPP; ++e)
        cnt += 1ull << ((row[e] & 7) * 8);

    // free-slot bitmask: slot p (= residue r, depth k) is free iff
    // k >= min(cnt[hostgroup], 8), hostgroup(r) = (r + c) & 7.
    unsigned long long freemask = 0ull;
#pragma unroll
    for (int r = 0; r < 8; ++r) {
        int hg = (r + c) & 7;
        int ch = (int)((cnt >> (hg * 8)) & 0xff);
        if (ch > 8) ch = 8;
        unsigned long long lowbits =
            (ch >= 8) ? ~0ull : ((1ull << (8 * ch)) - 1ull);
        freemask |= (PRE << r) & ~lowbits;
    }

    unsigned short* idx_out = (unsigned short*)g_idx;
    float*          w_out   = (float*)g_w;

    // pass 2: branch-free placement; spills pop freemask in entry order
    unsigned long long cur = 0ull;
    unsigned long long fm  = freemask;
#pragma unroll 4
    for (int e = 0; e < NSUPP; ++e) {
        int idx = row[e];
        int gg  = idx & 7;
        int j   = (int)((cur >> (gg * 8)) & 0xff);
        cur += 1ull << (gg * 8);

        bool isspill = (j >= 8);
        int pref = ((gg - c) & 7) + 8 * j;          // valid when j < 8
        int sp   = __ffsll((long long)fm) - 1;      // next free slot
        int slot = isspill ? sp : pref;
        fm       = isspill ? (fm & (fm - 1ull)) : fm;

        if (gg == g) {                               // predicated store
            idx_out[((slot >> 3) * NCLASS + c) * 8 + (slot & 7)] =
                (unsigned short)idx;
            w_out[((slot >> 2) * NCLASS + c) * 4 + (slot & 3)] = wrow[e];
        }
    }
}

__global__ void __launch_bounds__(THREADS, 3)
supp_kernel(const float* __restrict__ x, float* __restrict__ out) {
    // xs[idx] = x[b0..b0+3][idx]; gather bank group = idx&7.
    // Grid: 2 CTAs per batch tile; each handles 500 classes (halved work
    // quantum fills the last scheduling wave: 2048/456 slots -> 90% busy).
    extern __shared__ float4 smem[];
    float4* xs = smem;

    const int tile  = blockIdx.x >> 1;
    const int cbase = (blockIdx.x & 1) * CHALF;
    const int b0    = tile * NB;

    // --- Stage x tile: 4 rows x 4096 floats = 64 KB ---
    for (int i = threadIdx.x; i < NCHUNK; i += THREADS) {
        const float* xb = x + (size_t)b0 * NCHUNK + i;
        float t0 = xb[0 * NCHUNK];
        float t1 = xb[1 * NCHUNK];
        float t2 = xb[2 * NCHUNK];
        float t3 = xb[3 * NCHUNK];
        xs[i] = make_float4(t0, t1, t2, t3);
    }
    __syncthreads();

    // --- Gather + dot: thread = class (<=1 per thread), 4 batch rows ---
    // (8 consecutive classes per LDS phase -> schedule property holds for
    //  any class base; slot p of class c reads bank group (p+c)&7)
    if (threadIdx.x < CHALF) {
        const int c = cbase + threadIdx.x;
        float a0 = 0.f, a1 = 0.f, a2 = 0.f, a3 = 0.f;
#pragma unroll 2
        for (int k = 0; k < NSUPP / 8; ++k) {       // 8 entries per chunk
            int4   pi = g_idx[k * NCLASS + c];      // 8 u16 idx, LDG.128
            float4 wa = g_w[(2 * k) * NCLASS + c];  // slots 8k..8k+3
            float4 wb = g_w[(2 * k + 1) * NCLASS + c];

            int i0 = pi.x & 0xffff, i1 = ((unsigned)pi.x) >> 16;
            int i2 = pi.y & 0xffff, i3 = ((unsigned)pi.y) >> 16;
            int i4 = pi.z & 0xffff, i5 = ((unsigned)pi.z) >> 16;
            int i6 = pi.w & 0xffff, i7 = ((unsigned)pi.w) >> 16;

            float4 v;
            v = xs[i0]; a0 = fmaf(v.x, wa.x, a0); a1 = fmaf(v.y, wa.x, a1);
                        a2 = fmaf(v.z, wa.x, a2); a3 = fmaf(v.w, wa.x, a3);
            v = xs[i1]; a0 = fmaf(v.x, wa.y, a0); a1 = fmaf(v.y, wa.y, a1);
                        a2 = fmaf(v.z, wa.y, a2); a3 = fmaf(v.w, wa.y, a3);
            v = xs[i2]; a0 = fmaf(v.x, wa.z, a0); a1 = fmaf(v.y, wa.z, a1);
                        a2 = fmaf(v.z, wa.z, a2); a3 = fmaf(v.w, wa.z, a3);
            v = xs[i3]; a0 = fmaf(v.x, wa.w, a0); a1 = fmaf(v.y, wa.w, a1);
                        a2 = fmaf(v.z, wa.w, a2); a3 = fmaf(v.w, wa.w, a3);
            v = xs[i4]; a0 = fmaf(v.x, wb.x, a0); a1 = fmaf(v.y, wb.x, a1);
                        a2 = fmaf(v.z, wb.x, a2); a3 = fmaf(v.w, wb.x, a3);
            v = xs[i5]; a0 = fmaf(v.x, wb.y, a0); a1 = fmaf(v.y, wb.y, a1);
                        a2 = fmaf(v.z, wb.y, a2); a3 = fmaf(v.w, wb.y, a3);
            v = xs[i6]; a0 = fmaf(v.x, wb.z, a0); a1 = fmaf(v.y, wb.z, a1);
                        a2 = fmaf(v.z, wb.z, a2); a3 = fmaf(v.w, wb.z, a3);
            v = xs[i7]; a0 = fmaf(v.x, wb.w, a0); a1 = fmaf(v.y, wb.w, a1);
                        a2 = fmaf(v.z, wb.w, a2); a3 = fmaf(v.w, wb.w, a3);
        }

        float* o = out + (size_t)b0 * NCLASS + c;
        o[0 * NCLASS] = __expf(a0);
        o[1 * NCLASS] = __expf(a1);
        o[2 * NCLASS] = __expf(a2);
        o[3 * NCLASS] = __expf(a3);
    }
}

extern "C" void kernel_launch(void* const* d_in, const int* in_sizes, int n_in,
                              void* d_out, int out_size) {
    const float* x    = (const float*)d_in[0];  // [4096, 4096] f32
    const float* w    = (const float*)d_in[1];  // [1000, 64]   f32
    const int*   cmap = (const int*)d_in[2];    // [1000, 64]   i32
    float*       out  = (float*)d_out;          // [4096, 1000] f32

    (void)in_sizes; (void)n_in; (void)out_size;

    static const size_t smem_bytes = NCHUNK * sizeof(float4);  // 64 KB
    cudaFuncSetAttribute(supp_kernel,
                         cudaFuncAttributeMaxDynamicSharedMemorySize,
                         (int)smem_bytes);

    pack_kernel<<<(NCLASS * 8 + 127) / 128, 128>>>(w, cmap);
    supp_kernel<<<(BATCH / NB) * 2, THREADS, smem_bytes>>>(x, out);
}

// round 12
// speedup vs baseline: 1.1230x; 1.1230x over previous
#include <cuda_runtime.h>

// out[b,c] = exp( sum_s x[b, chunk_map[c,s]] * wSupp[c,s] )
// B=4096, NCLASS=1000, NSUPP=64, NCHUNK=4096

#define NCLASS 1000
#define NSUPP  64
#define NCHUNK 4096
#define BATCH  4096
#define NB     4       // batch rows per CTA (64 KB tile -> 3 CTAs/SM)
#define THREADS 544    // 17 warps; x3 CTAs = 51 warps/SM, 40-reg budget kept

// SoA packed schedule, transposed [chunk][class] for coalesced LDG:
//   g_idx: 8 u16 indices per int4   -> 8 chunks of 8 slots
//   g_w  : 4 f32 weights per float4 -> 16 chunks of 4 slots
// Schedule: slot p of class c prefers an entry with bank group
// (idx&7) == (p + c) & 7, so the 8 lanes of each LDS.128 phase
// (8 consecutive classes; THREADS % 8 == 0 keeps alignment) hit 8 distinct
// bank groups. Overflow entries (group count > 8) spill into leftover slots.
__device__ int4   g_idx[(NSUPP / 8) * NCLASS];
__device__ float4 g_w[(NSUPP / 4) * NCLASS];

// One thread per (class, bank-group). Branch-free: group counts and running
// ranks live in packed 8x8-bit u64 counters; spill slots come from a
// free-slot bitmask popped with ffsll (O(1) per spill, no inner scans).
__global__ void pack_kernel(const float* __restrict__ w,
                            const int* __restrict__ cmap) {
    int t = blockIdx.x * blockDim.x + threadIdx.x;
    if (t >= NCLASS * 8) return;
    int c = t >> 3;
    int g = t & 7;

    const int*   row  = cmap + c * NSUPP;
    const float* wrow = w + c * NSUPP;
    const unsigned long long PRE = 0x0101010101010101ull;

    // pass 1: per-group counts (8 counters x 8 bits in one u64)
    unsigned long long cnt = 0ull;
#pragma unroll 8
    for (int e = 0; e < NSUPP; ++e)
        cnt += 1ull << ((row[e] & 7) * 8);

    // free-slot bitmask: slot p (= residue r, depth k) is free iff
    // k >= min(cnt[hostgroup], 8), hostgroup(r) = (r + c) & 7.
    unsigned long long freemask = 0ull;
#pragma unroll
    for (int r = 0; r < 8; ++r) {
        int hg = (r + c) & 7;
        int ch = (int)((cnt >> (hg * 8)) & 0xff);
        if (ch > 8) ch = 8;
        unsigned long long lowbits =
            (ch >= 8) ? ~0ull : ((1ull << (8 * ch)) - 1ull);
        freemask |= (PRE << r) & ~lowbits;
    }

    unsigned short* idx_out = (unsigned short*)g_idx;
    float*          w_out   = (float*)g_w;

    // pass 2: branch-free placement; spills pop freemask in entry order
    unsigned long long cur = 0ull;
    unsigned long long fm  = freemask;
#pragma unroll 4
    for (int e = 0; e < NSUPP; ++e) {
        int idx = row[e];
        int gg  = idx & 7;
        int j   = (int)((cur >> (gg * 8)) & 0xff);
        cur += 1ull << (gg * 8);

        bool isspill = (j >= 8);
        int pref = ((gg - c) & 7) + 8 * j;          // valid when j < 8
        int sp   = __ffsll((long long)fm) - 1;      // next free slot
        int slot = isspill ? sp : pref;
        fm       = isspill ? (fm & (fm - 1ull)) : fm;

        if (gg == g) {                               // predicated store
            idx_out[((slot >> 3) * NCLASS + c) * 8 + (slot & 7)] =
                (unsigned short)idx;
            w_out[((slot >> 2) * NCLASS + c) * 4 + (slot & 3)] = wrow[e];
        }
    }
}

__global__ void __launch_bounds__(THREADS, 3)
supp_kernel(const float* __restrict__ x, float* __restrict__ out) {
    // xs[idx] = x[b0..b0+3][idx]; gather bank group = idx&7.
    extern __shared__ float4 smem[];
    float4* xs = smem;

    const int b0 = blockIdx.x * NB;

    // --- Stage x tile: 4 rows x 4096 floats = 64 KB ---
    for (int i = threadIdx.x; i < NCHUNK; i += THREADS) {
        const float* xb = x + (size_t)b0 * NCHUNK + i;
        float t0 = xb[0 * NCHUNK];
        float t1 = xb[1 * NCHUNK];
        float t2 = xb[2 * NCHUNK];
        float t3 = xb[3 * NCHUNK];
        xs[i] = make_float4(t0, t1, t2, t3);
    }
    __syncthreads();

    // --- Gather + dot: thread = class (<=2 per thread), 4 batch rows ---
    for (int c = threadIdx.x; c < NCLASS; c += THREADS) {
        float a0 = 0.f, a1 = 0.f, a2 = 0.f, a3 = 0.f;
#pragma unroll 2
        for (int k = 0; k < NSUPP / 8; ++k) {       // 8 entries per chunk
            int4   pi = g_idx[k * NCLASS + c];      // 8 u16 idx, LDG.128
            float4 wa = g_w[(2 * k) * NCLASS + c];  // slots 8k..8k+3
            float4 wb = g_w[(2 * k + 1) * NCLASS + c];

            int i0 = pi.x & 0xffff, i1 = ((unsigned)pi.x) >> 16;
            int i2 = pi.y & 0xffff, i3 = ((unsigned)pi.y) >> 16;
            int i4 = pi.z & 0xffff, i5 = ((unsigned)pi.z) >> 16;
            int i6 = pi.w & 0xffff, i7 = ((unsigned)pi.w) >> 16;

            float4 v;
            v = xs[i0]; a0 = fmaf(v.x, wa.x, a0); a1 = fmaf(v.y, wa.x, a1);
                        a2 = fmaf(v.z, wa.x, a2); a3 = fmaf(v.w, wa.x, a3);
            v = xs[i1]; a0 = fmaf(v.x, wa.y, a0); a1 = fmaf(v.y, wa.y, a1);
                        a2 = fmaf(v.z, wa.y, a2); a3 = fmaf(v.w, wa.y, a3);
            v = xs[i2]; a0 = fmaf(v.x, wa.z, a0); a1 = fmaf(v.y, wa.z, a1);
                        a2 = fmaf(v.z, wa.z, a2); a3 = fmaf(v.w, wa.z, a3);
            v = xs[i3]; a0 = fmaf(v.x, wa.w, a0); a1 = fmaf(v.y, wa.w, a1);
                        a2 = fmaf(v.z, wa.w, a2); a3 = fmaf(v.w, wa.w, a3);
            v = xs[i4]; a0 = fmaf(v.x, wb.x, a0); a1 = fmaf(v.y, wb.x, a1);
                        a2 = fmaf(v.z, wb.x, a2); a3 = fmaf(v.w, wb.x, a3);
            v = xs[i5]; a0 = fmaf(v.x, wb.y, a0); a1 = fmaf(v.y, wb.y, a1);
                        a2 = fmaf(v.z, wb.y, a2); a3 = fmaf(v.w, wb.y, a3);
            v = xs[i6]; a0 = fmaf(v.x, wb.z, a0); a1 = fmaf(v.y, wb.z, a1);
                        a2 = fmaf(v.z, wb.z, a2); a3 = fmaf(v.w, wb.z, a3);
            v = xs[i7]; a0 = fmaf(v.x, wb.w, a0); a1 = fmaf(v.y, wb.w, a1);
                        a2 = fmaf(v.z, wb.w, a2); a3 = fmaf(v.w, wb.w, a3);
        }

        float* o = out + (size_t)b0 * NCLASS + c;
        o[0 * NCLASS] = __expf(a0);
        o[1 * NCLASS] = __expf(a1);
        o[2 * NCLASS] = __expf(a2);
        o[3 * NCLASS] = __expf(a3);
    }
}

extern "C" void kernel_launch(void* const* d_in, const int* in_sizes, int n_in,
                              void* d_out, int out_size) {
    const float* x    = (const float*)d_in[0];  // [4096, 4096] f32
    const float* w    = (const float*)d_in[1];  // [1000, 64]   f32
    const int*   cmap = (const int*)d_in[2];    // [1000, 64]   i32
    float*       out  = (float*)d_out;          // [4096, 1000] f32

    (void)in_sizes; (void)n_in; (void)out_size;

    static const size_t smem_bytes = NCHUNK * sizeof(float4);  // 64 KB
    cudaFuncSetAttribute(supp_kernel,
                         cudaFuncAttributeMaxDynamicSharedMemorySize,
                         (int)smem_bytes);

    pack_kernel<<<(NCLASS * 8 + 127) / 128, 128>>>(w, cmap);
    supp_kernel<<<BATCH / NB, THREADS, smem_bytes>>>(x, out);
}

// round 13
// speedup vs baseline: 1.2583x; 1.1204x over previous
#include <cuda_runtime.h>

// out[b,c] = exp( sum_s x[b, chunk_map[c,s]] * wSupp[c,s] )
// B=4096, NCLASS=1000, NSUPP=64, NCHUNK=4096

#define NCLASS 1000
#define NSUPP  64
#define NCHUNK 4096
#define BATCH  4096
#define NB     4       // batch rows per CTA (64 KB tile -> 3 CTAs/SM)
#define THREADS 512

// SoA packed schedule, transposed [chunk][class] for coalesced LDG:
//   g_idx: 8 u16 indices per int4   -> 8 chunks of 8 slots
//   g_w  : 4 f32 weights per float4 -> 16 chunks of 4 slots
// Schedule: slot p of class c prefers an entry with bank group
// (idx&7) == (p + c) & 7, so the 8 lanes of each LDS.128 phase
// (8 consecutive classes) hit 8 distinct bank groups. Overflow entries
// (group count > 8) spill into leftover slots (~13%).
__device__ int4   g_idx[(NSUPP / 8) * NCLASS];
__device__ float4 g_w[(NSUPP / 4) * NCLASS];

// One thread per (class, bank-group). Branch-free: group counts and running
// ranks live in packed 8x8-bit u64 counters; spill slots come from a
// free-slot bitmask popped with ffsll (O(1) per spill, no inner scans).
__global__ void pack_kernel(const float* __restrict__ w,
                            const int* __restrict__ cmap) {
    int t = blockIdx.x * blockDim.x + threadIdx.x;
    if (t >= NCLASS * 8) return;
    int c = t >> 3;
    int g = t & 7;

    const int*   row  = cmap + c * NSUPP;
    const float* wrow = w + c * NSUPP;
    const unsigned long long PRE = 0x0101010101010101ull;

    // pass 1: per-group counts (8 counters x 8 bits in one u64)
    unsigned long long cnt = 0ull;
#pragma unroll 8
    for (int e = 0; e < NSUPP; ++e)
        cnt += 1ull << ((row[e] & 7) * 8);

    // free-slot bitmask: slot p (= residue r, depth k) is free iff
    // k >= min(cnt[hostgroup], 8), hostgroup(r) = (r + c) & 7.
    unsigned long long freemask = 0ull;
#pragma unroll
    for (int r = 0; r < 8; ++r) {
        int hg = (r + c) & 7;
        int ch = (int)((cnt >> (hg * 8)) & 0xff);
        if (ch > 8) ch = 8;
        unsigned long long lowbits =
            (ch >= 8) ? ~0ull : ((1ull << (8 * ch)) - 1ull);
        freemask |= (PRE << r) & ~lowbits;
    }

    unsigned short* idx_out = (unsigned short*)g_idx;
    float*          w_out   = (float*)g_w;

    // pass 2: branch-free placement; spills pop freemask in entry order
    unsigned long long cur = 0ull;
    unsigned long long fm  = freemask;
#pragma unroll 4
    for (int e = 0; e < NSUPP; ++e) {
        int idx = row[e];
        int gg  = idx & 7;
        int j   = (int)((cur >> (gg * 8)) & 0xff);
        cur += 1ull << (gg * 8);

        bool isspill = (j >= 8);
        int pref = ((gg - c) & 7) + 8 * j;          // valid when j < 8
        int sp   = __ffsll((long long)fm) - 1;      // next free slot
        int slot = isspill ? sp : pref;
        fm       = isspill ? (fm & (fm - 1ull)) : fm;

        if (gg == g) {                               // predicated store
            idx_out[((slot >> 3) * NCLASS + c) * 8 + (slot & 7)] =
                (unsigned short)idx;
            w_out[((slot >> 2) * NCLASS + c) * 4 + (slot & 3)] = wrow[e];
        }
    }
}

__global__ void __launch_bounds__(THREADS, 3)
supp_kernel(const float* __restrict__ x, float* __restrict__ out) {
    // xs[idx] = x[b0..b0+3][idx]; gather bank group = idx&7.
    extern __shared__ float4 smem[];
    float4* xs = smem;

    const int b0 = blockIdx.x * NB;

    // --- Stage x tile: 4 rows x 4096 floats = 64 KB ---
    for (int i = threadIdx.x; i < NCHUNK; i += THREADS) {
        const float* xb = x + (size_t)b0 * NCHUNK + i;
        float t0 = xb[0 * NCHUNK];
        float t1 = xb[1 * NCHUNK];
        float t2 = xb[2 * NCHUNK];
        float t3 = xb[3 * NCHUNK];
        xs[i] = make_float4(t0, t1, t2, t3);
    }
    __syncthreads();

    // --- Gather + dot: thread = class (2 per thread), 4 batch rows each ---
    for (int c = threadIdx.x; c < NCLASS; c += THREADS) {
        float a0 = 0.f, a1 = 0.f, a2 = 0.f, a3 = 0.f;
#pragma unroll 4
        for (int k = 0; k < NSUPP / 8; ++k) {       // 8 entries per chunk
            int4   pi = g_idx[k * NCLASS + c];      // 8 u16 idx, LDG.128
            float4 wa = g_w[(2 * k) * NCLASS + c];  // slots 8k..8k+3
            float4 wb = g_w[(2 * k + 1) * NCLASS + c];

            int i0 = pi.x & 0xffff, i1 = ((unsigned)pi.x) >> 16;
            int i2 = pi.y & 0xffff, i3 = ((unsigned)pi.y) >> 16;
            int i4 = pi.z & 0xffff, i5 = ((unsigned)pi.z) >> 16;
            int i6 = pi.w & 0xffff, i7 = ((unsigned)pi.w) >> 16;

            float4 v;
            v = xs[i0]; a0 = fmaf(v.x, wa.x, a0); a1 = fmaf(v.y, wa.x, a1);
                        a2 = fmaf(v.z, wa.x, a2); a3 = fmaf(v.w, wa.x, a3);
            v = xs[i1]; a0 = fmaf(v.x, wa.y, a0); a1 = fmaf(v.y, wa.y, a1);
                        a2 = fmaf(v.z, wa.y, a2); a3 = fmaf(v.w, wa.y, a3);
            v = xs[i2]; a0 = fmaf(v.x, wa.z, a0); a1 = fmaf(v.y, wa.z, a1);
                        a2 = fmaf(v.z, wa.z, a2); a3 = fmaf(v.w, wa.z, a3);
            v = xs[i3]; a0 = fmaf(v.x, wa.w, a0); a1 = fmaf(v.y, wa.w, a1);
                        a2 = fmaf(v.z, wa.w, a2); a3 = fmaf(v.w, wa.w, a3);
            v = xs[i4]; a0 = fmaf(v.x, wb.x, a0); a1 = fmaf(v.y, wb.x, a1);
                        a2 = fmaf(v.z, wb.x, a2); a3 = fmaf(v.w, wb.x, a3);
            v = xs[i5]; a0 = fmaf(v.x, wb.y, a0); a1 = fmaf(v.y, wb.y, a1);
                        a2 = fmaf(v.z, wb.y, a2); a3 = fmaf(v.w, wb.y, a3);
            v = xs[i6]; a0 = fmaf(v.x, wb.z, a0); a1 = fmaf(v.y, wb.z, a1);
                        a2 = fmaf(v.z, wb.z, a2); a3 = fmaf(v.w, wb.z, a3);
            v = xs[i7]; a0 = fmaf(v.x, wb.w, a0); a1 = fmaf(v.y, wb.w, a1);
                        a2 = fmaf(v.z, wb.w, a2); a3 = fmaf(v.w, wb.w, a3);
        }

        float* o = out + (size_t)b0 * NCLASS + c;
        o[0 * NCLASS] = __expf(a0);
        o[1 * NCLASS] = __expf(a1);
        o[2 * NCLASS] = __expf(a2);
        o[3 * NCLASS] = __expf(a3);
    }
}

extern "C" void kernel_launch(void* const* d_in, const int* in_sizes, int n_in,
                              void* d_out, int out_size) {
    const float* x    = (const float*)d_in[0];  // [4096, 4096] f32
    const float* w    = (const float*)d_in[1];  // [1000, 64]   f32
    const int*   cmap = (const int*)d_in[2];    // [1000, 64]   i32
    float*       out  = (float*)d_out;          // [4096, 1000] f32

    (void)in_sizes; (void)n_in; (void)out_size;

    static const size_t smem_bytes = NCHUNK * sizeof(float4);  // 64 KB
    cudaFuncSetAttribute(supp_kernel,
                         cudaFuncAttributeMaxDynamicSharedMemorySize,
                         (int)smem_bytes);

    pack_kernel<<<(NCLASS * 8 + 127) / 128, 128>>>(w, cmap);
    supp_kernel<<<BATCH / NB, THREADS, smem_bytes>>>(x, out);
}

// round 14
// speedup vs baseline: 1.3288x; 1.0561x over previous
#include <cuda_runtime.h>

// out[b,c] = exp( sum_s x[b, chunk_map[c,s]] * wSupp[c,s] )
// B=4096, NCLASS=1000, NSUPP=64, NCHUNK=4096

#define NCLASS 1000
#define NSUPP  64
#define NCHUNK 4096
#define BATCH  4096
#define NB     4       // batch rows per CTA (64 KB tile -> 3 CTAs/SM)
#define THREADS 512

// Fused schedule entries, transposed [chunk][class] for coalesced LDG.128:
// one u32 per (class, slot):  [w_fix:20 | idx:12]
//   w_fix = rint(w * 2^19)  (w in [-1,1) -> fits signed 20 bits exactly)
//   idx   = chunk index (< 4096, 12 bits)
// Accumulation runs 2^19-scaled; the scale is folded into the final expf.
// Schedule: slot p of class c prefers an entry with bank group
// (idx&7) == (p + c) & 7, so the 8 lanes of each LDS.128 phase
// (8 consecutive classes) hit 8 distinct bank groups. Overflow entries
// (group count > 8) spill into leftover slots (~13%).
__device__ int4 g_u[(NSUPP / 4) * NCLASS];   // 4 entries per int4

// One thread per (class, bank-group). Branch-free: group counts and running
// ranks live in packed 8x8-bit u64 counters; spill slots come from a
// free-slot bitmask popped with ffsll (O(1) per spill, no inner scans).
__global__ void pack_kernel(const float* __restrict__ w,
                            const int* __restrict__ cmap) {
    int t = blockIdx.x * blockDim.x + threadIdx.x;
    if (t >= NCLASS * 8) return;
    int c = t >> 3;
    int g = t & 7;

    const int*   row  = cmap + c * NSUPP;
    const float* wrow = w + c * NSUPP;
    const unsigned long long PRE = 0x0101010101010101ull;

    // pass 1: per-group counts (8 counters x 8 bits in one u64)
    unsigned long long cnt = 0ull;
#pragma unroll 8
    for (int e = 0; e < NSUPP; ++e)
        cnt += 1ull << ((row[e] & 7) * 8);

    // free-slot bitmask: slot p (= residue r, depth k) is free iff
    // k >= min(cnt[hostgroup], 8), hostgroup(r) = (r + c) & 7.
    unsigned long long freemask = 0ull;
#pragma unroll
    for (int r = 0; r < 8; ++r) {
        int hg = (r + c) & 7;
        int ch = (int)((cnt >> (hg * 8)) & 0xff);
        if (ch > 8) ch = 8;
        unsigned long long lowbits =
            (ch >= 8) ? ~0ull : ((1ull << (8 * ch)) - 1ull);
        freemask |= (PRE << r) & ~lowbits;
    }

    unsigned* u_out = (unsigned*)g_u;

    // pass 2: branch-free placement; spills pop freemask in entry order
    unsigned long long cur = 0ull;
    unsigned long long fm  = freemask;
#pragma unroll 4
    for (int e = 0; e < NSUPP; ++e) {
        int idx = row[e];
        int gg  = idx & 7;
        int j   = (int)((cur >> (gg * 8)) & 0xff);
        cur += 1ull << (gg * 8);

        bool isspill = (j >= 8);
        int pref = ((gg - c) & 7) + 8 * j;          // valid when j < 8
        int sp   = __ffsll((long long)fm) - 1;      // next free slot
        int slot = isspill ? sp : pref;
        fm       = isspill ? (fm & (fm - 1ull)) : fm;

        if (gg == g) {                               // predicated store
            int wfix = __float2int_rn(wrow[e] * 524288.f);  // w * 2^19
            unsigned enc = (((unsigned)wfix) << 12) | (unsigned)(idx & 0xfff);
            u_out[((slot >> 2) * NCLASS + c) * 4 + (slot & 3)] = enc;
        }
    }
}

__device__ __forceinline__ void gstep(unsigned u, const float4* xs,
                                      float& a0, float& a1,
                                      float& a2, float& a3) {
    int   idx = (int)(u & 0xfffu);
    float wf  = (float)(((int)u) >> 12);   // w * 2^19
    float4 v  = xs[idx];
    a0 = fmaf(v.x, wf, a0);
    a1 = fmaf(v.y, wf, a1);
    a2 = fmaf(v.z, wf, a2);
    a3 = fmaf(v.w, wf, a3);
}

__global__ void __launch_bounds__(THREADS, 3)
supp_kernel(const float* __restrict__ x, float* __restrict__ out) {
    // xs[idx] = x[b0..b0+3][idx]; gather bank group = idx&7.
    extern __shared__ float4 smem[];
    float4* xs = smem;

    const int b0 = blockIdx.x * NB;

    // --- Stage x tile: 4 rows x 4096 floats = 64 KB ---
    for (int i = threadIdx.x; i < NCHUNK; i += THREADS) {
        const float* xb = x + (size_t)b0 * NCHUNK + i;
        float t0 = xb[0 * NCHUNK];
        float t1 = xb[1 * NCHUNK];
        float t2 = xb[2 * NCHUNK];
        float t3 = xb[3 * NCHUNK];
        xs[i] = make_float4(t0, t1, t2, t3);
    }
    __syncthreads();

    // --- Gather + dot: thread = class (2 per thread), 4 batch rows each ---
    for (int c = threadIdx.x; c < NCLASS; c += THREADS) {
        float a0 = 0.f, a1 = 0.f, a2 = 0.f, a3 = 0.f;
#pragma unroll 4
        for (int k = 0; k < NSUPP / 8; ++k) {        // 8 entries per chunk
            int4 ua = g_u[(2 * k) * NCLASS + c];     // 4 fused entries
            int4 ub = g_u[(2 * k + 1) * NCLASS + c]; // 4 fused entries
            gstep((unsigned)ua.x, xs, a0, a1, a2, a3);
            gstep((unsigned)ua.y, xs, a0, a1, a2, a3);
            gstep((unsigned)ua.z, xs, a0, a1, a2, a3);
            gstep((unsigned)ua.w, xs, a0, a1, a2, a3);
            gstep((unsigned)ub.x, xs, a0, a1, a2, a3);
            gstep((unsigned)ub.y, xs, a0, a1, a2, a3);
            gstep((unsigned)ub.z, xs, a0, a1, a2, a3);
            gstep((unsigned)ub.w, xs, a0, a1, a2, a3);
        }

        const float S = 1.f / 524288.f;              // fold back 2^-19
        float* o = out + (size_t)b0 * NCLASS + c;
        o[0 * NCLASS] = __expf(a0 * S);
        o[1 * NCLASS] = __expf(a1 * S);
        o[2 * NCLASS] = __expf(a2 * S);
        o[3 * NCLASS] = __expf(a3 * S);
    }
}

extern "C" void kernel_launch(void* const* d_in, const int* in_sizes, int n_in,
                              void* d_out, int out_size) {
    const float* x    = (const float*)d_in[0];  // [4096, 4096] f32
    const float* w    = (const float*)d_in[1];  // [1000, 64]   f32
    const int*   cmap = (const int*)d_in[2];    // [1000, 64]   i32
    float*       out  = (float*)d_out;          // [4096, 1000] f32

    (void)in_sizes; (void)n_in; (void)out_size;

    static const size_t smem_bytes = NCHUNK * sizeof(float4);  // 64 KB
    cudaFuncSetAttribute(supp_kernel,
                         cudaFuncAttributeMaxDynamicSharedMemorySize,
                         (int)smem_bytes);

    pack_kernel<<<(NCLASS * 8 + 127) / 128, 128>>>(w, cmap);
    supp_kernel<<<BATCH / NB, THREADS, smem_bytes>>>(x, out);
}

// round 15
// speedup vs baseline: 1.3615x; 1.0246x over previous
#include <cuda_runtime.h>

// out[b,c] = exp( sum_s x[b, chunk_map[c,s]] * wSupp[c,s] )
// B=4096, NCLASS=1000, NSUPP=64, NCHUNK=4096

#define NCLASS 1000
#define NSUPP  64
#define NCHUNK 4096
#define BATCH  4096
#define NB     4       // batch rows per CTA (64 KB tile -> 3 CTAs/SM)
#define THREADS 512

// Fused schedule entries, transposed [chunk][class] for coalesced LDG.128:
// one u32 per (class, slot):  [w_fix:20 | idx:12]
//   w_fix = rint(w * 2^19)  (w in [-1,1) -> fits signed 20 bits exactly)
//   idx   = chunk index (< 4096, 12 bits)
// Accumulation runs 2^19-scaled; the scale is folded into the final expf.
// Schedule: slot p of class c prefers an entry with bank group
// (idx&7) == (p + c) & 7, so the 8 lanes of each LDS.128 phase
// (8 consecutive classes) hit 8 distinct bank groups. Overflow entries
// (group count > 8) spill into leftover slots (~13%).
__device__ int4 g_u[(NSUPP / 4) * NCLASS];   // 4 entries per int4

// One thread per (class, bank-group). Branch-free; cmap row read as int4
// (16 LDG.128 per pass instead of 64 LDG.32). Group counts and running
// ranks live in packed 8x8-bit u64 counters; spill slots come from a
// free-slot bitmask popped with ffsll (O(1) per spill, no inner scans).
__global__ void pack_kernel(const float* __restrict__ w,
                            const int* __restrict__ cmap) {
    int t = blockIdx.x * blockDim.x + threadIdx.x;
    if (t >= NCLASS * 8) return;
    int c = t >> 3;
    int g = t & 7;

    const int4*  row4 = (const int4*)(cmap + c * NSUPP);
    const float* wrow = w + c * NSUPP;
    const unsigned long long PRE = 0x0101010101010101ull;

    // pass 1: per-group counts (8 counters x 8 bits in one u64)
    unsigned long long cnt = 0ull;
#pragma unroll 4
    for (int e4 = 0; e4 < NSUPP / 4; ++e4) {
        int4 q = row4[e4];
        cnt += 1ull << ((q.x & 7) * 8);
        cnt += 1ull << ((q.y & 7) * 8);
        cnt += 1ull << ((q.z & 7) * 8);
        cnt += 1ull << ((q.w & 7) * 8);
    }

    // free-slot bitmask: slot p (= residue r, depth k) is free iff
    // k >= min(cnt[hostgroup], 8), hostgroup(r) = (r + c) & 7.
    unsigned long long freemask = 0ull;
#pragma unroll
    for (int r = 0; r < 8; ++r) {
        int hg = (r + c) & 7;
        int ch = (int)((cnt >> (hg * 8)) & 0xff);
        if (ch > 8) ch = 8;
        unsigned long long lowbits =
            (ch >= 8) ? ~0ull : ((1ull << (8 * ch)) - 1ull);
        freemask |= (PRE << r) & ~lowbits;
    }

    unsigned* u_out = (unsigned*)g_u;

    // pass 2: branch-free placement; spills pop freemask in entry order
    unsigned long long cur = 0ull;
    unsigned long long fm  = freemask;
#pragma unroll 4
    for (int e4 = 0; e4 < NSUPP / 4; ++e4) {
        int4 q = row4[e4];
#pragma unroll
        for (int u = 0; u < 4; ++u) {
            int idx = (u == 0) ? q.x : (u == 1) ? q.y : (u == 2) ? q.z : q.w;
            int e   = e4 * 4 + u;
            int gg  = idx & 7;
            int j   = (int)((cur >> (gg * 8)) & 0xff);
            cur += 1ull << (gg * 8);

            bool isspill = (j >= 8);
            int pref = ((gg - c) & 7) + 8 * j;          // valid when j < 8
            int sp   = __ffsll((long long)fm) - 1;      // next free slot
            int slot = isspill ? sp : pref;
            fm       = isspill ? (fm & (fm - 1ull)) : fm;

            if (gg == g) {                               // predicated store
                int wfix = __float2int_rn(wrow[e] * 524288.f);  // w * 2^19
                unsigned enc =
                    (((unsigned)wfix) << 12) | (unsigned)(idx & 0xfff);
                u_out[((slot >> 2) * NCLASS + c) * 4 + (slot & 3)] = enc;
            }
        }
    }
}

__device__ __forceinline__ void gstep(unsigned u, const float4* xs,
                                      float& a0, float& a1,
                                      float& a2, float& a3) {
    int   idx = (int)(u & 0xfffu);
    float wf  = (float)(((int)u) >> 12);   // w * 2^19
    float4 v  = xs[idx];
    a0 = fmaf(v.x, wf, a0);
    a1 = fmaf(v.y, wf, a1);
    a2 = fmaf(v.z, wf, a2);
    a3 = fmaf(v.w, wf, a3);
}

__global__ void __launch_bounds__(THREADS, 3)
supp_kernel(const float* __restrict__ x, float* __restrict__ out) {
    // xs[idx] = x[b0..b0+3][idx]; gather bank group = idx&7.
    extern __shared__ float4 smem[];
    float4* xs = smem;

    const int b0 = blockIdx.x * NB;

    // --- Stage x tile: 4 rows x 4096 floats = 64 KB ---
    for (int i = threadIdx.x; i < NCHUNK; i += THREADS) {
        const float* xb = x + (size_t)b0 * NCHUNK + i;
        float t0 = xb[0 * NCHUNK];
        float t1 = xb[1 * NCHUNK];
        float t2 = xb[2 * NCHUNK];
        float t3 = xb[3 * NCHUNK];
        xs[i] = make_float4(t0, t1, t2, t3);
    }
    __syncthreads();

    // --- Gather + dot: thread = class (2 per thread), 4 batch rows each ---
    for (int c = threadIdx.x; c < NCLASS; c += THREADS) {
        float a0 = 0.f, a1 = 0.f, a2 = 0.f, a3 = 0.f;
#pragma unroll 4
        for (int k = 0; k < NSUPP / 8; ++k) {        // 8 entries per chunk
            int4 ua = g_u[(2 * k) * NCLASS + c];     // 4 fused entries
            int4 ub = g_u[(2 * k + 1) * NCLASS + c]; // 4 fused entries
            gstep((unsigned)ua.x, xs, a0, a1, a2, a3);
            gstep((unsigned)ua.y, xs, a0, a1, a2, a3);
            gstep((unsigned)ua.z, xs, a0, a1, a2, a3);
            gstep((unsigned)ua.w, xs, a0, a1, a2, a3);
            gstep((unsigned)ub.x, xs, a0, a1, a2, a3);
            gstep((unsigned)ub.y, xs, a0, a1, a2, a3);
            gstep((unsigned)ub.z, xs, a0, a1, a2, a3);
            gstep((unsigned)ub.w, xs, a0, a1, a2, a3);
        }

        const float S = 1.f / 524288.f;              // fold back 2^-19
        float* o = out + (size_t)b0 * NCLASS + c;
        o[0 * NCLASS] = __expf(a0 * S);
        o[1 * NCLASS] = __expf(a1 * S);
        o[2 * NCLASS] = __expf(a2 * S);
        o[3 * NCLASS] = __expf(a3 * S);
    }
}

extern "C" void kernel_launch(void* const* d_in, const int* in_sizes, int n_in,
                              void* d_out, int out_size) {
    const float* x    = (const float*)d_in[0];  // [4096, 4096] f32
    const float* w    = (const float*)d_in[1];  // [1000, 64]   f32
    const int*   cmap = (const int*)d_in[2];    // [1000, 64]   i32
    float*       out  = (float*)d_out;          // [4096, 1000] f32

    (void)in_sizes; (void)n_in; (void)out_size;

    static const size_t smem_bytes = NCHUNK * sizeof(float4);  // 64 KB
    cudaFuncSetAttribute(supp_kernel,
                         cudaFuncAttributeMaxDynamicSharedMemorySize,
                         (int)smem_bytes);

    pack_kernel<<<(NCLASS * 8 + 127) / 128, 128>>>(w, cmap);
    supp_kernel<<<BATCH / NB, THREADS, smem_bytes>>>(x, out);
}

// round 16
// speedup vs baseline: 1.3628x; 1.0010x over previous
#include <cuda_runtime.h>

// out[b,c] = exp( sum_s x[b, chunk_map[c,s]] * wSupp[c,s] )
// B=4096, NCLASS=1000, NSUPP=64, NCHUNK=4096

#define NCLASS 1000
#define NSUPP  64
#define NCHUNK 4096
#define BATCH  4096
#define NB     4       // batch rows per CTA (64 KB tile -> 3 CTAs/SM)
#define THREADS 512

// Fused schedule entries, transposed [chunk][class] for coalesced LDG.128:
// one u32 per (class, slot):  [w_fix:20 | idx:12]
//   w_fix = rint(w * 2^19)  (w in [-1,1) -> fits signed 20 bits exactly)
//   idx   = chunk index (< 4096, 12 bits)
// Accumulation runs 2^19-scaled; the scale is folded into the final expf.
// Schedule: slot p of class c prefers an entry with bank group
// (idx&7) == (p + c) & 7, so the 8 lanes of each LDS.128 phase
// (8 consecutive classes) hit 8 distinct bank groups. Overflow entries
// (group count > 8) spill into leftover slots (~13%).
__device__ int4 g_u[(NSUPP / 4) * NCLASS];   // 4 entries per int4

// One thread per (class, bank-group). Branch-free; cmap row read as int4.
// Triggers programmatic launch completion immediately so supp_kernel can
// start its (g_u-independent) tile-fill prologue concurrently; supp's
// cudaGridDependencySynchronize() provides the real completion barrier.
__global__ void pack_kernel(const float* __restrict__ w,
                            const int* __restrict__ cmap) {
#if __CUDA_ARCH__ >= 900
    cudaTriggerProgrammaticLaunchCompletion();
#endif
    int t = blockIdx.x * blockDim.x + threadIdx.x;
    if (t >= NCLASS * 8) return;
    int c = t >> 3;
    int g = t & 7;

    const int4*  row4 = (const int4*)(cmap + c * NSUPP);
    const float* wrow = w + c * NSUPP;
    const unsigned long long PRE = 0x0101010101010101ull;

    // pass 1: per-group counts (8 counters x 8 bits in one u64)
    unsigned long long cnt = 0ull;
#pragma unroll 4
    for (int e4 = 0; e4 < NSUPP / 4; ++e4) {
        int4 q = row4[e4];
        cnt += 1ull << ((q.x & 7) * 8);
        cnt += 1ull << ((q.y & 7) * 8);
        cnt += 1ull << ((q.z & 7) * 8);
        cnt += 1ull << ((q.w & 7) * 8);
    }

    // free-slot bitmask: slot p (= residue r, depth k) is free iff
    // k >= min(cnt[hostgroup], 8), hostgroup(r) = (r + c) & 7.
    unsigned long long freemask = 0ull;
#pragma unroll
    for (int r = 0; r < 8; ++r) {
        int hg = (r + c) & 7;
        int ch = (int)((cnt >> (hg * 8)) & 0xff);
        if (ch > 8) ch = 8;
        unsigned long long lowbits =
            (ch >= 8) ? ~0ull : ((1ull << (8 * ch)) - 1ull);
        freemask |= (PRE << r) & ~lowbits;
    }

    unsigned* u_out = (unsigned*)g_u;

    // pass 2: branch-free placement; spills pop freemask in entry order
    unsigned long long cur = 0ull;
    unsigned long long fm  = freemask;
#pragma unroll 4
    for (int e4 = 0; e4 < NSUPP / 4; ++e4) {
        int4 q = row4[e4];
#pragma unroll
        for (int u = 0; u < 4; ++u) {
            int idx = (u == 0) ? q.x : (u == 1) ? q.y : (u == 2) ? q.z : q.w;
            int e   = e4 * 4 + u;
            int gg  = idx & 7;
            int j   = (int)((cur >> (gg * 8)) & 0xff);
            cur += 1ull << (gg * 8);

            bool isspill = (j >= 8);
            int pref = ((gg - c) & 7) + 8 * j;          // valid when j < 8
            int sp   = __ffsll((long long)fm) - 1;      // next free slot
            int slot = isspill ? sp : pref;
            fm       = isspill ? (fm & (fm - 1ull)) : fm;

            if (gg == g) {                               // predicated store
                int wfix = __float2int_rn(wrow[e] * 524288.f);  // w * 2^19
                unsigned enc =
                    (((unsigned)wfix) << 12) | (unsigned)(idx & 0xfff);
                u_out[((slot >> 2) * NCLASS + c) * 4 + (slot & 3)] = enc;
            }
        }
    }
}

__device__ __forceinline__ void gstep(unsigned u, const float4* xs,
                                      float& a0, float& a1,
                                      float& a2, float& a3) {
    int   idx = (int)(u & 0xfffu);
    float wf  = (float)(((int)u) >> 12);   // w * 2^19
    float4 v  = xs[idx];
    a0 = fmaf(v.x, wf, a0);
    a1 = fmaf(v.y, wf, a1);
    a2 = fmaf(v.z, wf, a2);
    a3 = fmaf(v.w, wf, a3);
}

__global__ void __launch_bounds__(THREADS, 3)
supp_kernel(const float* __restrict__ x, float* __restrict__ out) {
    // xs[idx] = x[b0..b0+3][idx]; gather bank group = idx&7.
    extern __shared__ float4 smem[];
    float4* xs = smem;

    const int b0 = blockIdx.x * NB;

    // --- Stage x tile (independent of pack output; overlaps pack via PDL) ---
    for (int i = threadIdx.x; i < NCHUNK; i += THREADS) {
        const float* xb = x + (size_t)b0 * NCHUNK + i;
        float t0 = xb[0 * NCHUNK];
        float t1 = xb[1 * NCHUNK];
        float t2 = xb[2 * NCHUNK];
        float t3 = xb[3 * NCHUNK];
        xs[i] = make_float4(t0, t1, t2, t3);
    }
    __syncthreads();

#if __CUDA_ARCH__ >= 900
    cudaGridDependencySynchronize();   // wait for pack completion (g_u ready)
#endif

    // --- Gather + dot: thread = class (2 per thread), 4 batch rows each ---
    for (int c = threadIdx.x; c < NCLASS; c += THREADS) {
        float a0 = 0.f, a1 = 0.f, a2 = 0.f, a3 = 0.f;
#pragma unroll 4
        for (int k = 0; k < NSUPP / 8; ++k) {        // 8 entries per chunk
            int4 ua = g_u[(2 * k) * NCLASS + c];     // 4 fused entries
            int4 ub = g_u[(2 * k + 1) * NCLASS + c]; // 4 fused entries
            gstep((unsigned)ua.x, xs, a0, a1, a2, a3);
            gstep((unsigned)ua.y, xs, a0, a1, a2, a3);
            gstep((unsigned)ua.z, xs, a0, a1, a2, a3);
            gstep((unsigned)ua.w, xs, a0, a1, a2, a3);
            gstep((unsigned)ub.x, xs, a0, a1, a2, a3);
            gstep((unsigned)ub.y, xs, a0, a1, a2, a3);
            gstep((unsigned)ub.z, xs, a0, a1, a2, a3);
            gstep((unsigned)ub.w, xs, a0, a1, a2, a3);
        }

        const float S = 1.f / 524288.f;              // fold back 2^-19
        float* o = out + (size_t)b0 * NCLASS + c;
        o[0 * NCLASS] = __expf(a0 * S);
        o[1 * NCLASS] = __expf(a1 * S);
        o[2 * NCLASS] = __expf(a2 * S);
        o[3 * NCLASS] = __expf(a3 * S);
    }
}

extern "C" void kernel_launch(void* const* d_in, const int* in_sizes, int n_in,
                              void* d_out, int out_size) {
    const float* x    = (const float*)d_in[0];  // [4096, 4096] f32
    const float* w    = (const float*)d_in[1];  // [1000, 64]   f32
    const int*   cmap = (const int*)d_in[2];    // [1000, 64]   i32
    float*       out  = (float*)d_out;          // [4096, 1000] f32

    (void)in_sizes; (void)n_in; (void)out_size;

    static const size_t smem_bytes = NCHUNK * sizeof(float4);  // 64 KB
    cudaFuncSetAttribute(supp_kernel,
                         cudaFuncAttributeMaxDynamicSharedMemorySize,
                         (int)smem_bytes);

    pack_kernel<<<(NCLASS * 8 + 127) / 128, 128>>>(w, cmap);

    // PDL launch: supp may start (fill phase) while pack is still running;
    // its cudaGridDependencySynchronize() enforces the g_u dependency.
    cudaLaunchConfig_t cfg = {};
    cfg.gridDim  = dim3(BATCH / NB);
    cfg.blockDim = dim3(THREADS);
    cfg.dynamicSmemBytes = smem_bytes;
    cfg.stream = 0;
    cudaLaunchAttribute attr[1];
    attr[0].id = cudaLaunchAttributeProgrammaticStreamSerialization;
    attr[0].val.programmaticStreamSerializationAllowed = 1;
    cfg.attrs = attr;
    cfg.numAttrs = 1;
    cudaLaunchKernelEx(&cfg, supp_kernel, x, out);
}